// round 3
// baseline (speedup 1.0000x reference)
#include <cuda_runtime.h>

// ---------- f32x2 packed helpers (sm_103a; PTX-only per SASS_QUICKREF) ----------
typedef unsigned long long f2;

__device__ __forceinline__ f2 pk(float lo, float hi) {
    f2 r; asm("mov.b64 %0,{%1,%2};" : "=l"(r) : "f"(lo), "f"(hi)); return r;
}
__device__ __forceinline__ void upk(f2 v, float& lo, float& hi) {
    asm("mov.b64 {%0,%1},%2;" : "=f"(lo), "=f"(hi) : "l"(v));
}
__device__ __forceinline__ f2 add2(f2 a, f2 b) {
    f2 r; asm("add.rn.f32x2 %0,%1,%2;" : "=l"(r) : "l"(a), "l"(b)); return r;
}
__device__ __forceinline__ f2 mul2(f2 a, f2 b) {
    f2 r; asm("mul.rn.f32x2 %0,%1,%2;" : "=l"(r) : "l"(a), "l"(b)); return r;
}
__device__ __forceinline__ f2 fma2(f2 a, f2 b, f2 c) {
    f2 r; asm("fma.rn.f32x2 %0,%1,%2,%3;" : "=l"(r) : "l"(a), "l"(b), "l"(c)); return r;
}

// Fused gate G_q = [CNOT·]CRX·(H⊗I) on local packed bits (LO, HI).
// Hadamard WITHOUT the 1/sqrt2 factor (folded into final probability scale 2^-12).
// CRX uses s = -i*sin: x = s*u + c*v, y = c*u + s*v on the control==1 pair (u=amp[b], v=amp[d]).
// With CNOT: amp[b]=x, amp[d]=y.  Without (last gate): amp[b]=y, amp[d]=x.
template<int LO, int HI, bool CNOT>
__device__ __forceinline__ void stepP(f2 (&R)[16], f2 (&I)[16],
                                      f2 n1, f2 cv, f2 sv, f2 nsv) {
#pragma unroll
    for (int m = 0; m < 16; ++m) {
        if (m & ((1 << LO) | (1 << HI))) continue;
        const int a = m, b = m | (1 << LO), c = m | (1 << HI), d = b | (1 << HI);
        f2 t;
        // unnormalized H butterflies on LO
        t = add2(R[a], R[b]); R[b] = fma2(n1, R[b], R[a]); R[a] = t;
        t = add2(I[a], I[b]); I[b] = fma2(n1, I[b], I[a]); I[a] = t;
        t = add2(R[c], R[d]); R[d] = fma2(n1, R[d], R[c]); R[c] = t;
        t = add2(I[c], I[d]); I[d] = fma2(n1, I[d], I[c]); I[c] = t;
        // CRX (+CNOT) on (b, d)
        f2 xr = fma2(sv,  I[b], mul2(cv, R[d]));   // re(s*u + c*v)
        f2 xi = fma2(nsv, R[b], mul2(cv, I[d]));   // im(s*u + c*v)
        f2 yr = fma2(sv,  I[d], mul2(cv, R[b]));   // re(c*u + s*v)
        f2 yi = fma2(nsv, R[d], mul2(cv, I[b]));   // im(c*u + s*v)
        if (CNOT) { R[b] = xr; I[b] = xi; R[d] = yr; I[d] = yi; }
        else      { R[b] = yr; I[b] = yi; R[d] = xr; I[d] = xi; }
    }
}

// conflict-free SMEM swizzle
__device__ __forceinline__ int sw(int i) { return i ^ ((i >> 5) & 31); }

// amp index maps per phase; thread t (0..127), local l (0..31); spare = l bit 4
#define AMP0(T,L) (((T) << 5) | (L))                                   // local abs bits 0-4
#define AMP1(T,L) ((((T) >> 3) << 8) | ((L) << 3) | ((T) & 7))          // local abs bits 3-7
#define AMP2(T,L) ((((T) >> 6) << 11) | ((L) << 6) | ((T) & 63))        // local abs bits 6-10
#define AMP3(T,L) ((((L) & 7) << 9) | ((T) << 2) | ((L) >> 3))          // local abs {9,10,11,0,1}

__global__ void __launch_bounds__(128, 4)
quantum_kernel(const float* __restrict__ x,
               const float* __restrict__ prm,
               float* __restrict__ out) {
    __shared__ float2 buf[4096];      // 32 KB transpose buffer
    __shared__ float2 cs[12];
    __shared__ float rsum[4], rcnt[4];
    __shared__ float s_ninv, s_sc;

    const int t = threadIdx.x, lane = t & 31, w = t >> 5;
    const float* xr = x + (size_t)blockIdx.x * 4096;

    // load 32 consecutive floats (each thread consumes whole 128B line)
    float v[32];
#pragma unroll
    for (int k = 0; k < 8; ++k) {
        float4 q = *reinterpret_cast<const float4*>(xr + t * 32 + k * 4);
        v[4*k] = q.x; v[4*k+1] = q.y; v[4*k+2] = q.z; v[4*k+3] = q.w;
    }
    if (t < 12) { float th = prm[t] * 0.5f; cs[t] = make_float2(cosf(th), sinf(th)); }

    // row reduction: sum of squares + nonzero count
    float ss = 0.f, cn = 0.f;
#pragma unroll
    for (int j = 0; j < 32; ++j) {
        ss += v[j] * v[j];
        cn += (v[j] != 0.f) ? 1.f : 0.f;
    }
#pragma unroll
    for (int m = 16; m >= 1; m >>= 1) {
        ss += __shfl_xor_sync(~0u, ss, m);
        cn += __shfl_xor_sync(~0u, cn, m);
    }
    if (lane == 0) { rsum[w] = ss; rcnt[w] = cn; }
    __syncthreads();
    if (t == 0) {
        float S = rsum[0] + rsum[1] + rsum[2] + rsum[3];
        float C = rcnt[0] + rcnt[1] + rcnt[2] + rcnt[3];
        s_ninv = 1.f / (sqrtf(S) + 1e-8f);
        // 1/||q||^2 * (1/sqrt2)^24 from the 12 folded Hadamards
        s_sc = (C > 0.f ? 1.f / C : 0.f) * (1.f / 4096.f);
    }
    __syncthreads();
    const float ninv = s_ninv;

    // _to_quantum: sr = clamp(x*ninv, -1, 1) (== sgn*mag); si = sgn*sqrt(1-sr^2)
    f2 R[16], I[16];
#pragma unroll
    for (int j = 0; j < 16; ++j) {
        float x0 = v[j], x1 = v[j + 16];
        float r0 = fminf(fmaxf(x0 * ninv, -1.f), 1.f);
        float r1 = fminf(fmaxf(x1 * ninv, -1.f), 1.f);
        float g0 = (x0 > 0.f) ? 1.f : ((x0 < 0.f) ? -1.f : 0.f);
        float g1 = (x1 > 0.f) ? 1.f : ((x1 < 0.f) ? -1.f : 0.f);
        float i0 = g0 * sqrtf(fmaxf(1.f - r0 * r0, 0.f));
        float i1 = g1 * sqrtf(fmaxf(1.f - r1 * r1, 0.f));
        R[j] = pk(r0, r1); I[j] = pk(i0, i1);
    }

    const f2 n1 = pk(-1.f, -1.f);

#define STEP(Q,LO,HI,CN) { float2 g = cs[Q]; \
    f2 cv = pk(g.x, g.x), sv = pk(g.y, g.y), nsv = pk(-g.y, -g.y); \
    stepP<LO,HI,CN>(R, I, n1, cv, sv, nsv); }

#define XPOSE(AW, AR) { \
    _Pragma("unroll") for (int j = 0; j < 16; ++j) { \
        float rl, rh, il, ih; upk(R[j], rl, rh); upk(I[j], il, ih); \
        buf[sw(AW(t, j))]        = make_float2(rl, il); \
        buf[sw(AW(t, (j | 16)))] = make_float2(rh, ih); } \
    __syncthreads(); \
    _Pragma("unroll") for (int j = 0; j < 16; ++j) { \
        float2 a = buf[sw(AR(t, j))]; \
        float2 b = buf[sw(AR(t, (j | 16)))]; \
        R[j] = pk(a.x, b.x); I[j] = pk(a.y, b.y); } \
    __syncthreads(); }

    // Phase 0: gates q=0,1,2 on abs bits (0,1),(1,2),(2,3)
    STEP(0, 0, 1, true) STEP(1, 1, 2, true) STEP(2, 2, 3, true)
    XPOSE(AMP0, AMP1)
    // Phase 1: q=3,4,5 on abs (3,4),(4,5),(5,6)
    STEP(3, 0, 1, true) STEP(4, 1, 2, true) STEP(5, 2, 3, true)
    XPOSE(AMP1, AMP2)
    // Phase 2: q=6,7,8 on abs (6,7),(7,8),(8,9)
    STEP(6, 0, 1, true) STEP(7, 1, 2, true) STEP(8, 2, 3, true)
    XPOSE(AMP2, AMP3)
    // Phase 3: q=9,10 on abs (9,10),(10,11); q=11 on abs (11,0) WITHOUT CNOT
    STEP(9, 0, 1, true) STEP(10, 1, 2, true) STEP(11, 2, 3, false)

    // probabilities (scaled), staged through SMEM for coalesced global stores
    const float sc = s_sc;
    const f2 scv = pk(sc, sc);
    float* pb = reinterpret_cast<float*>(buf);
#pragma unroll
    for (int j = 0; j < 16; ++j) {
        f2 p2 = mul2(fma2(R[j], R[j], mul2(I[j], I[j])), scv);
        float pl, ph; upk(p2, pl, ph);
        pb[sw(AMP3(t, j))]        = pl;
        pb[sw(AMP3(t, (j | 16)))] = ph;
    }
    __syncthreads();
    float* orow = out + (size_t)blockIdx.x * 4096;
#pragma unroll
    for (int k = 0; k < 8; ++k) {
        int b0 = t * 32 + k * 4;
        float4 o;
        o.x = pb[sw(b0)]; o.y = pb[sw(b0 + 1)];
        o.z = pb[sw(b0 + 2)]; o.w = pb[sw(b0 + 3)];
        *reinterpret_cast<float4*>(orow + b0) = o;
    }
}

extern "C" void kernel_launch(void* const* d_in, const int* in_sizes, int n_in,
                              void* d_out, int out_size) {
    const float* state  = (const float*)d_in[0];
    const float* params = (const float*)d_in[1];
    float* out = (float*)d_out;
    int rows = in_sizes[0] / 4096;   // 4096 rows
    quantum_kernel<<<rows, 128>>>(state, params, out);
}

// round 4
// speedup vs baseline: 1.3521x; 1.3521x over previous
#include <cuda_runtime.h>

__device__ __forceinline__ float fsqrt_ap(float x) {
    float r; asm("sqrt.approx.f32 %0, %1;" : "=f"(r) : "f"(x)); return r;
}

// Fused gate G_q = [CNOT·]CRX·(H⊗I) on local bits (LO=control/H bit, HI=target).
// H is UNNORMALIZED (1/sqrt2 folded into final 2^-12 prob scale).
// CRX column mix with s-coef = -i*sin: on control==1 pair (u=amp[b], v=amp[d]):
//   x = s*u + c*v (new target-1 comp), y = c*u + s*v (new target-0 comp)
// CNOT then swaps: amp[b]=x, amp[d]=y.  Last gate (no CNOT): amp[b]=y, amp[d]=x.
template<int LO, int HI, bool CNOT>
__device__ __forceinline__ void step(float (&R)[16], float (&I)[16],
                                     float c, float s) {
    constexpr int L0 = 1 << LO, L1 = 1 << HI;
#pragma unroll
    for (int m = 0; m < 16; ++m) {
        if (m & (L0 | L1)) continue;
        const int a = m, b = m | L0, e = m | L1, d = m | L0 | L1;
        float t0;
        // unnormalized H butterflies on LO
        t0 = R[a] + R[b]; R[b] = R[a] - R[b]; R[a] = t0;
        t0 = I[a] + I[b]; I[b] = I[a] - I[b]; I[a] = t0;
        t0 = R[e] + R[d]; R[d] = R[e] - R[d]; R[e] = t0;
        t0 = I[e] + I[d]; I[d] = I[e] - I[d]; I[e] = t0;
        // CRX (+CNOT) on (b, d):  s*u = (sn*ui) - i*(sn*ur)
        float xr = fmaf(s,  I[b], c * R[d]);
        float xi = fmaf(-s, R[b], c * I[d]);
        float yr = fmaf(s,  I[d], c * R[b]);
        float yi = fmaf(-s, R[d], c * I[b]);
        if (CNOT) { R[b] = xr; I[b] = xi; R[d] = yr; I[d] = yi; }
        else      { R[b] = yr; I[b] = yi; R[d] = xr; I[d] = xi; }
    }
}

// conflict-free SMEM swizzle (float2 elements; mixes bits 9:5 into 4:0)
__device__ __forceinline__ int sw(int i) { return i ^ ((i >> 5) & 31); }

// amp-index maps: thread t (0..255), local slot j (0..15)
#define AMP0(T,J) (((T) << 4) | (J))                                  // abs bits 0-3 local
#define AMP1(T,J) ((((T) >> 3) << 7) | ((J) << 3) | ((T) & 7))        // abs bits 3-6 local
#define AMP2(T,J) ((((T) >> 6) << 10) | ((J) << 6) | ((T) & 63))      // abs bits 6-9 local
#define AMP3(T,J) ((((J) & 7) << 9) | ((T) << 1) | ((J) >> 3))        // abs {9,10,11 | 0} local

__global__ void __launch_bounds__(256, 4)
quantum_kernel(const float* __restrict__ x,
               const float* __restrict__ prm,
               float* __restrict__ out) {
    __shared__ float2 buf[4096];           // 32 KB transpose buffer
    __shared__ float2 cs[12];
    __shared__ float rsum[8], rcnt[8];
    __shared__ float s_ninv, s_sc;

    const int t = threadIdx.x, lane = t & 31, w = t >> 5;
    const float* __restrict__ xr = x + (size_t)blockIdx.x * 4096;

    // load 16 consecutive floats: abs index = t*16 + j  (phase-0 layout)
    float v[16];
#pragma unroll
    for (int k = 0; k < 4; ++k) {
        float4 q = *reinterpret_cast<const float4*>(xr + t * 16 + k * 4);
        v[4*k] = q.x; v[4*k+1] = q.y; v[4*k+2] = q.z; v[4*k+3] = q.w;
    }
    if (t < 12) { float th = prm[t] * 0.5f; cs[t] = make_float2(cosf(th), sinf(th)); }

    // row reduction: sum of squares + nonzero count
    float ss = 0.f, cn = 0.f;
#pragma unroll
    for (int j = 0; j < 16; ++j) {
        ss = fmaf(v[j], v[j], ss);
        cn += (v[j] != 0.f) ? 1.f : 0.f;
    }
#pragma unroll
    for (int m = 16; m >= 1; m >>= 1) {
        ss += __shfl_xor_sync(~0u, ss, m);
        cn += __shfl_xor_sync(~0u, cn, m);
    }
    if (lane == 0) { rsum[w] = ss; rcnt[w] = cn; }
    __syncthreads();
    if (t == 0) {
        float S = 0.f, C = 0.f;
#pragma unroll
        for (int k = 0; k < 8; ++k) { S += rsum[k]; C += rcnt[k]; }
        s_ninv = 1.f / (fsqrt_ap(S) + 1e-8f);
        // 1/||q||^2  *  (1/sqrt2)^24 from the 12 folded Hadamards
        s_sc = (C > 0.f ? 1.f / C : 0.f) * (1.f / 4096.f);
    }
    __syncthreads();
    const float ninv = s_ninv;

    // _to_quantum: re = clamp(x*ninv,-1,1) = sgn*mag ; im = sgn*sqrt(1-re^2)
    float R[16], I[16];
#pragma unroll
    for (int j = 0; j < 16; ++j) {
        float xv = v[j];
        float r  = fminf(fmaxf(xv * ninv, -1.f), 1.f);
        float g  = (xv > 0.f) ? 1.f : ((xv < 0.f) ? -1.f : 0.f);
        R[j] = r;
        I[j] = g * fsqrt_ap(fmaxf(fmaf(-r, r, 1.f), 0.f));
    }

#define STEP(Q,LO,HI,CN) { float2 g = cs[Q]; step<LO,HI,CN>(R, I, g.x, g.y); }

#define XPOSE(AW, AR) { \
    _Pragma("unroll") for (int j = 0; j < 16; ++j) \
        buf[sw(AW(t, j))] = make_float2(R[j], I[j]); \
    __syncthreads(); \
    _Pragma("unroll") for (int j = 0; j < 16; ++j) { \
        float2 a = buf[sw(AR(t, j))]; \
        R[j] = a.x; I[j] = a.y; } \
    __syncthreads(); }

    // Phase 0: q=0,1,2 on abs (0,1),(1,2),(2,3)
    STEP(0, 0, 1, true) STEP(1, 1, 2, true) STEP(2, 2, 3, true)
    XPOSE(AMP0, AMP1)
    // Phase 1: q=3,4,5 on abs (3,4),(4,5),(5,6) -> local (0,1),(1,2),(2,3)
    STEP(3, 0, 1, true) STEP(4, 1, 2, true) STEP(5, 2, 3, true)
    XPOSE(AMP1, AMP2)
    // Phase 2: q=6,7,8 on abs (6,7),(7,8),(8,9)
    STEP(6, 0, 1, true) STEP(7, 1, 2, true) STEP(8, 2, 3, true)
    XPOSE(AMP2, AMP3)
    // Phase 3: q=9,10 on abs (9,10),(10,11); q=11 on abs (11,0), NO CNOT
    STEP(9, 0, 1, true) STEP(10, 1, 2, true) STEP(11, 2, 3, false)

    // output: AMP3(t,j) = (j&7)<<9 | t<<1 | (j>>3)  ->  (prob[j], prob[j|8])
    // is a float2 at offset (j<<9) + (t<<1): perfectly coalesced per warp.
    const float sc = s_sc;
    float* __restrict__ orow = out + (size_t)blockIdx.x * 4096;
#pragma unroll
    for (int j = 0; j < 8; ++j) {
        float2 p;
        p.x = (fmaf(R[j], R[j], I[j] * I[j])) * sc;
        p.y = (fmaf(R[j+8], R[j+8], I[j+8] * I[j+8])) * sc;
        *reinterpret_cast<float2*>(orow + (j << 9) + (t << 1)) = p;
    }
}

extern "C" void kernel_launch(void* const* d_in, const int* in_sizes, int n_in,
                              void* d_out, int out_size) {
    const float* state  = (const float*)d_in[0];
    const float* params = (const float*)d_in[1];
    float* out = (float*)d_out;
    int rows = in_sizes[0] / 4096;   // 4096 rows
    quantum_kernel<<<rows, 256>>>(state, params, out);
}

// round 5
// speedup vs baseline: 1.5568x; 1.1514x over previous
#include <cuda_runtime.h>

__device__ __forceinline__ float fsqrt_ap(float x) {
    float r; asm("sqrt.approx.f32 %0, %1;" : "=f"(r) : "f"(x)); return r;
}
__device__ __forceinline__ float sx(float v, int m) {
    return __shfl_xor_sync(0xFFFFFFFFu, v, m, 32);
}

// Fused gate G_q = CNOT·CRX·(H⊗I) on local bits (LO=control, HI=target).
// H unnormalized (1/sqrt2^24 folded into final prob scale).
template<int LO, int HI>
__device__ __forceinline__ void step_local(float (&R)[16], float (&I)[16],
                                           float c, float s) {
    constexpr int L0 = 1 << LO, L1 = 1 << HI;
#pragma unroll
    for (int m = 0; m < 16; ++m) {
        if (m & (L0 | L1)) continue;
        const int a = m, b = m | L0, e = m | L1, d = m | L0 | L1;
        float t0;
        t0 = R[a] + R[b]; R[b] = R[a] - R[b]; R[a] = t0;
        t0 = I[a] + I[b]; I[b] = I[a] - I[b]; I[a] = t0;
        t0 = R[e] + R[d]; R[d] = R[e] - R[d]; R[e] = t0;
        t0 = I[e] + I[d]; I[d] = I[e] - I[d]; I[e] = t0;
        // CRX (s = -i*sin) then CNOT swap on (b,d)
        float xr = fmaf(s,  I[b], c * R[d]);
        float xi = fmaf(-s, R[b], c * I[d]);
        float yr = fmaf(s,  I[d], c * R[b]);
        float yi = fmaf(-s, R[d], c * I[b]);
        R[b] = xr; I[b] = xi; R[d] = yr; I[d] = yi;
    }
}

// Gate with control = local bit 3, target = lane bit (mask M).
// With CNOT the combined update is symmetric: new = s*self + c*partner.
// FINAL (q=11, no CNOT): new = c*self + s*partner.
template<bool FINAL>
__device__ __forceinline__ void step_shfl(float (&R)[16], float (&I)[16],
                                          float c, float s, int M) {
#pragma unroll
    for (int m = 0; m < 8; ++m) {      // H on local bit 3
        const int a = m, b = m | 8;
        float t0;
        t0 = R[a] + R[b]; R[b] = R[a] - R[b]; R[a] = t0;
        t0 = I[a] + I[b]; I[b] = I[a] - I[b]; I[a] = t0;
    }
#pragma unroll
    for (int m = 8; m < 16; ++m) {     // CRX(+CNOT) across lane bit, control==1
        float mr = R[m], mi = I[m];
        float pr = sx(mr, M), pi = sx(mi, M);
        if (FINAL) {
            R[m] = fmaf(c, mr,  s * pi);
            I[m] = fmaf(c, mi, -s * pr);
        } else {
            R[m] = fmaf(s,  mi, c * pr);
            I[m] = fmaf(-s, mr, c * pi);
        }
    }
}

// conflict-free SMEM swizzle for all four access patterns below
__device__ __forceinline__ int sw(int i) { return i ^ ((i >> 4) & 31); }

// amp-index maps: thread t (0..255), local slot j (0..15)
#define AMPA(T,J) (((T) << 4) | (J))                                   // abs 0-3 local, bit4=lane0
#define AMPB(T,J) (((T) & 15) | ((J) << 4) | (((T) >> 4) << 8))        // abs 4-7 local, bit8=lane4
#define AMPC(T,J) (((T) & 255) | ((J) << 8))                           // abs 8-11 local, bit0=lane0

__global__ void __launch_bounds__(256, 4)
quantum_kernel(const float* __restrict__ x,
               const float* __restrict__ prm,
               float* __restrict__ out) {
    __shared__ float2 buf[4096];           // 32 KB transpose buffer
    __shared__ float2 cs[12];
    __shared__ float rsum[8], rcnt[8];
    __shared__ float s_ninv, s_sc;

    const int t = threadIdx.x, lane = t & 31, w = t >> 5;
    const float* __restrict__ xr = x + (size_t)blockIdx.x * 4096;

    // load 16 consecutive floats: abs index = t*16 + j (phase-A layout)
    float v[16];
#pragma unroll
    for (int k = 0; k < 4; ++k) {
        float4 q = *reinterpret_cast<const float4*>(xr + t * 16 + k * 4);
        v[4*k] = q.x; v[4*k+1] = q.y; v[4*k+2] = q.z; v[4*k+3] = q.w;
    }
    if (t < 12) { float th = prm[t] * 0.5f; cs[t] = make_float2(cosf(th), sinf(th)); }

    // row reduction: sum of squares + nonzero count
    float ss = 0.f, cn = 0.f;
#pragma unroll
    for (int j = 0; j < 16; ++j) {
        ss = fmaf(v[j], v[j], ss);
        cn += (v[j] != 0.f) ? 1.f : 0.f;
    }
#pragma unroll
    for (int m = 16; m >= 1; m >>= 1) {
        ss += sx(ss, m);
        cn += sx(cn, m);
    }
    if (lane == 0) { rsum[w] = ss; rcnt[w] = cn; }
    __syncthreads();
    if (t == 0) {
        float S = 0.f, C = 0.f;
#pragma unroll
        for (int k = 0; k < 8; ++k) { S += rsum[k]; C += rcnt[k]; }
        s_ninv = 1.f / (sqrtf(S) + 1e-8f);
        // 1/||q||^2 * (1/sqrt2)^24 from 12 folded Hadamards
        s_sc = (C > 0.f ? 1.f / C : 0.f) * (1.f / 4096.f);
    }
    __syncthreads();
    const float ninv = s_ninv;

    // _to_quantum: re = clamp(x*ninv,-1,1) = sgn*mag; im = sgn*sqrt(1-re^2)
    float R[16], I[16];
#pragma unroll
    for (int j = 0; j < 16; ++j) {
        float xv = v[j];
        float r  = fminf(fmaxf(xv * ninv, -1.f), 1.f);
        float g  = (xv > 0.f) ? 1.f : ((xv < 0.f) ? -1.f : 0.f);
        R[j] = r;
        I[j] = g * fsqrt_ap(fmaxf(fmaf(-r, r, 1.f), 0.f));
    }

#define LSTEP(Q,LO,HI) { float2 g = cs[Q]; step_local<LO,HI>(R, I, g.x, g.y); }
#define SSTEP(Q,M,F)   { float2 g = cs[Q]; step_shfl<F>(R, I, g.x, g.y, M); }

#define XPOSE(AW, AR) { \
    _Pragma("unroll") for (int j = 0; j < 16; ++j) \
        buf[sw(AW(t, j))] = make_float2(R[j], I[j]); \
    __syncthreads(); \
    _Pragma("unroll") for (int j = 0; j < 16; ++j) { \
        float2 a = buf[sw(AR(t, j))]; \
        R[j] = a.x; I[j] = a.y; } \
    __syncthreads(); }

    // Phase A: q=0,1,2 local on abs (0,1),(1,2),(2,3); q=3 on (3,4): lane bit0
    LSTEP(0, 0, 1) LSTEP(1, 1, 2) LSTEP(2, 2, 3)
    SSTEP(3, 1, false)
    XPOSE(AMPA, AMPB)
    // Phase B: q=4,5,6 local on abs (4,5),(5,6),(6,7); q=7 on (7,8): lane bit4
    LSTEP(4, 0, 1) LSTEP(5, 1, 2) LSTEP(6, 2, 3)
    SSTEP(7, 16, false)
    XPOSE(AMPB, AMPC)
    // Phase C: q=8,9,10 local on abs (8,9),(9,10),(10,11); q=11 on (11,0): lane bit0, NO CNOT
    LSTEP(8, 0, 1) LSTEP(9, 1, 2) LSTEP(10, 2, 3)
    SSTEP(11, 1, true)

    // output: abs = (j<<8) | t — consecutive t per j => fully coalesced 128B/warp
    const float sc = s_sc;
    float* __restrict__ orow = out + (size_t)blockIdx.x * 4096;
#pragma unroll
    for (int j = 0; j < 16; ++j) {
        orow[(j << 8) | t] = fmaf(R[j], R[j], I[j] * I[j]) * sc;
    }
}

extern "C" void kernel_launch(void* const* d_in, const int* in_sizes, int n_in,
                              void* d_out, int out_size) {
    const float* state  = (const float*)d_in[0];
    const float* params = (const float*)d_in[1];
    float* out = (float*)d_out;
    int rows = in_sizes[0] / 4096;   // 4096 rows
    quantum_kernel<<<rows, 256>>>(state, params, out);
}